// round 10
// baseline (speedup 1.0000x reference)
#include <cuda_runtime.h>
#include <cuda_bf16.h>
#include <cooperative_groups.h>
#include <cstdint>

namespace cg = cooperative_groups;

// Problem constants
#define BB 128          // batch
#define SS 1024         // seq
#define II 768          // input dim
#define HH 256          // hidden
#define OO 6            // output
#define MM (BB * SS)    // 131072 rows
#define G3 (3 * HH)     // 768 gate rows

#define KA   1536       // packed A' cols = [hi(768) | lo(768)] bf16
#define KAB  (KA * 2)   // 3072 bytes per A' row
#define KP   2304       // logical K' = 3*768 (B' rows keep full [Wh|Wl|Wh])
#define KPB  (KP * 2)   // 4608 bytes per B' row
#define NCHUNK 36       // K' / 64
#define NSTG 3
#define STG_BYTES 32768 // A 16KB + B 16KB

typedef unsigned long long ull;

// ---------------------------------------------------------------------------
// Scratch (device globals — allocation-free rule)
// ---------------------------------------------------------------------------
__device__ __align__(128) float g_xg[(size_t)MM * G3];           // [M, 768]
__device__ __align__(128) float g_hs[(size_t)MM * HH];           // [M, 256]
__device__ __align__(128) __nv_bfloat16 g_ax[(size_t)MM * KA];   // packed A' [hi|lo]
__device__ __align__(128) __nv_bfloat16 g_bx[(size_t)G3 * KP];   // packed B' [Wh|Wl|Wh]

// ---------------------------------------------------------------------------
// Generic-PTX helpers
// ---------------------------------------------------------------------------
__device__ __forceinline__ uint32_t smem_u32(const void* p) {
    uint32_t r;
    asm("{ .reg .u64 t; cvta.to.shared.u64 t, %1; cvt.u32.u64 %0, t; }"
        : "=r"(r) : "l"(p));
    return r;
}

__device__ __forceinline__ void cpa16(uint32_t saddr, const char* g) {
    asm volatile("cp.async.cg.shared.global [%0], [%1], 16;" :: "r"(saddr), "l"(g));
}

#define LDSM_X4(r, addr) \
    asm volatile("ldmatrix.sync.aligned.m8n8.x4.shared.b16 {%0,%1,%2,%3}, [%4];" \
                 : "=r"((r)[0]), "=r"((r)[1]), "=r"((r)[2]), "=r"((r)[3]) : "r"(addr))

#define MMA_16816(d, a, b0, b1) \
    asm volatile("mma.sync.aligned.m16n8k16.row.col.f32.bf16.bf16.f32 " \
                 "{%0,%1,%2,%3}, {%4,%5,%6,%7}, {%8,%9}, {%0,%1,%2,%3};" \
                 : "+f"((d)[0]), "+f"((d)[1]), "+f"((d)[2]), "+f"((d)[3]) \
                 : "r"((a)[0]), "r"((a)[1]), "r"((a)[2]), "r"((a)[3]), \
                   "r"(b0), "r"(b1))

#define FMA2(acc, a, b) \
    asm("fma.rn.f32x2 %0, %1, %2, %0;" : "+l"(acc) : "l"(a), "l"(b))

#define MBAR_INIT(addr, cnt) \
    asm volatile("mbarrier.init.shared.b64 [%0], %1;" :: "r"(addr), "r"(cnt) : "memory")

#define MBAR_EXPECT_TX(addr, tx) \
    asm volatile("mbarrier.arrive.expect_tx.shared.b64 _, [%0], %1;" \
                 :: "r"(addr), "r"(tx) : "memory")

#define MBAR_WAIT_CL(addr, parity) do {                                        \
    uint32_t _m = (addr); uint32_t _p = (parity); uint32_t _d;                 \
    asm volatile("{\n\t.reg .pred p;\n\t"                                      \
        "mbarrier.try_wait.parity.acquire.cluster.shared::cta.b64 p, [%1], %2;\n\t" \
        "selp.b32 %0, 1, 0, p;\n\t}"                                           \
        : "=r"(_d) : "r"(_m), "r"(_p) : "memory");                             \
    if (!_d) {                                                                 \
        asm volatile("{\n\t.reg .pred P1;\n\t"                                 \
            "W_%=:\n\t"                                                        \
            "mbarrier.try_wait.parity.acquire.cluster.shared::cta.b64 P1, [%0], %1, 0x989680;\n\t" \
            "@P1 bra.uni D_%=;\n\t"                                            \
            "bra.uni W_%=;\n\t"                                                \
            "D_%=:\n\t}" :: "r"(_m), "r"(_p) : "memory");                      \
    }                                                                          \
} while (0)

#define ST_ASYNC_F32(raddr, val, rmbar) \
    asm volatile("st.async.shared::cluster.mbarrier::complete_tx::bytes.b32 [%0], %1, [%2];" \
                 :: "r"(raddr), "r"(__float_as_uint(val)), "r"(rmbar) : "memory")

#define MAPA_U32(out, local, rank) \
    asm("mapa.shared::cluster.u32 %0, %1, %2;" : "=r"(out) : "r"(local), "r"(rank))

// ===========================================================================
// Convert kernels: A' = [hi(768) | lo(768)], B' = [Wh | Wl | Wh]
// ===========================================================================
__global__ __launch_bounds__(192) void convert_x_kernel(const float* __restrict__ x)
{
    const size_t row = blockIdx.x;
    const int t = threadIdx.x;
    float4 v = __ldg((const float4*)(x + row * II) + t);
    __nv_bfloat16 h0 = __float2bfloat16_rn(v.x);
    __nv_bfloat16 h1 = __float2bfloat16_rn(v.y);
    __nv_bfloat16 h2 = __float2bfloat16_rn(v.z);
    __nv_bfloat16 h3 = __float2bfloat16_rn(v.w);
    __nv_bfloat16 l0 = __float2bfloat16_rn(v.x - __bfloat162float(h0));
    __nv_bfloat16 l1 = __float2bfloat16_rn(v.y - __bfloat162float(h1));
    __nv_bfloat16 l2 = __float2bfloat16_rn(v.z - __bfloat162float(h2));
    __nv_bfloat16 l3 = __float2bfloat16_rn(v.w - __bfloat162float(h3));
    __nv_bfloat162 hp0 = __halves2bfloat162(h0, h1);
    __nv_bfloat162 hp1 = __halves2bfloat162(h2, h3);
    __nv_bfloat162 lp0 = __halves2bfloat162(l0, l1);
    __nv_bfloat162 lp1 = __halves2bfloat162(l2, l3);
    // row = 1536 bf16 = 768 bf162: hi at bf162 [0,384), lo at [384,768)
    __nv_bfloat162* base = (__nv_bfloat162*)(g_ax + row * KA);
    base[t * 2]       = hp0;  base[t * 2 + 1]       = hp1;
    base[384 + t * 2] = lp0;  base[384 + t * 2 + 1] = lp1;
}

__global__ __launch_bounds__(192) void convert_w_kernel(const float* __restrict__ W)
{
    const size_t row = blockIdx.x;
    const int t = threadIdx.x;
    float4 v = __ldg((const float4*)(W + row * II) + t);
    __nv_bfloat16 h0 = __float2bfloat16_rn(v.x);
    __nv_bfloat16 h1 = __float2bfloat16_rn(v.y);
    __nv_bfloat16 h2 = __float2bfloat16_rn(v.z);
    __nv_bfloat16 h3 = __float2bfloat16_rn(v.w);
    __nv_bfloat16 l0 = __float2bfloat16_rn(v.x - __bfloat162float(h0));
    __nv_bfloat16 l1 = __float2bfloat16_rn(v.y - __bfloat162float(h1));
    __nv_bfloat16 l2 = __float2bfloat16_rn(v.z - __bfloat162float(h2));
    __nv_bfloat16 l3 = __float2bfloat16_rn(v.w - __bfloat162float(h3));
    __nv_bfloat162 hp0 = __halves2bfloat162(h0, h1);
    __nv_bfloat162 hp1 = __halves2bfloat162(h2, h3);
    __nv_bfloat162 lp0 = __halves2bfloat162(l0, l1);
    __nv_bfloat162 lp1 = __halves2bfloat162(l2, l3);
    // B' = [Wh | Wl | Wh] pairs with A' chunks [hi | hi | lo]
    __nv_bfloat162* base = (__nv_bfloat162*)(g_bx + row * KP);
    base[t * 2]       = hp0;  base[t * 2 + 1]       = hp1;
    base[384 + t * 2] = lp0;  base[384 + t * 2 + 1] = lp1;
    base[768 + t * 2] = hp0;  base[768 + t * 2 + 1] = hp1;
}

// ===========================================================================
// Kernel 1: xg = x @ W_ih^T + b_ih via mma.sync bf16 (BN=128).
// A' stored as [hi|lo] (3072 B/row); chunk c -> hi (c<12), hi again
// (12..23, L2-hot re-read), lo (24..35).
// ===========================================================================
__device__ __forceinline__ int a_src_off(int c) {
    return (c < 12) ? c * 128 : ((c < 24) ? (c - 12) * 128 : 1536 + (c - 24) * 128);
}

__global__ __launch_bounds__(256, 1) void gemm_mma_kernel(
    const float* __restrict__ bias)
{
    extern __shared__ __align__(1024) char dsm[];
    __shared__ float s_bias[128];

    const int tid  = threadIdx.x;
    const int lane = tid & 31;
    const int warp = tid >> 5;
    const int wm = warp >> 2;
    const int wn = warp & 3;
    const int n0 = blockIdx.x * 128;
    const size_t m0 = (size_t)blockIdx.y * 128;

    const uint32_t smem_base = smem_u32(dsm);

    if (tid < 128) s_bias[tid] = __ldg(bias + n0 + tid);

    const char* gA = (const char*)(g_ax) + m0 * KAB;
    const char* gB = (const char*)(g_bx) + (size_t)n0 * KPB;

    auto issue_loads = [&](int slot, int chunk) {
        const uint32_t stgA = smem_base + slot * STG_BYTES;
        const uint32_t stgB = stgA + 16384;
        const int abyte = a_src_off(chunk);
        const int bbyte = chunk * 128;
#pragma unroll
        for (int i = 0; i < 4; i++) {
            int seg = tid + i * 256;
            int r = seg >> 3, c = seg & 7;
            uint32_t off = (uint32_t)(r * 128 + ((c ^ (r & 7)) << 4));
            cpa16(stgA + off, gA + (size_t)r * KAB + abyte + c * 16);
            cpa16(stgB + off, gB + (size_t)r * KPB + bbyte + c * 16);
        }
    };

    const int lrow = (lane & 7) + ((lane >> 3) & 1) * 8;
    const int cp   = lane >> 4;
    const int arow = wm * 64 + lrow;
    const int brow = wn * 32 + lrow;

    float acc[4][4][4];
#pragma unroll
    for (int f = 0; f < 4; f++)
#pragma unroll
        for (int g = 0; g < 4; g++)
#pragma unroll
            for (int r = 0; r < 4; r++) acc[f][g][r] = 0.0f;

    issue_loads(0, 0);
    asm volatile("cp.async.commit_group;" ::: "memory");
    issue_loads(1, 1);
    asm volatile("cp.async.commit_group;" ::: "memory");

    for (int c = 0; c < NCHUNK; c++) {
        const int lc = c + 2;
        if (lc < NCHUNK) issue_loads(lc % NSTG, lc);
        asm volatile("cp.async.commit_group;" ::: "memory");
        asm volatile("cp.async.wait_group 2;" ::: "memory");
        __syncthreads();

        const uint32_t stgA = smem_base + (c % NSTG) * STG_BYTES;
        const uint32_t stgB = stgA + 16384;

#pragma unroll
        for (int s = 0; s < 4; s++) {
            const int ach = ((2 * s + cp) ^ (arow & 7)) << 4;
            const int bch = ((2 * s + cp) ^ (brow & 7)) << 4;
            uint32_t a[4][4];
            uint32_t b[2][4];
#pragma unroll
            for (int f = 0; f < 4; f++)
                LDSM_X4(a[f], stgA + (uint32_t)((arow + f * 16) * 128 + ach));
#pragma unroll
            for (int g2 = 0; g2 < 2; g2++)
                LDSM_X4(b[g2], stgB + (uint32_t)((brow + g2 * 16) * 128 + bch));
#pragma unroll
            for (int f = 0; f < 4; f++) {
#pragma unroll
                for (int g = 0; g < 4; g++)
                    MMA_16816(acc[f][g], a[f], b[g >> 1][g & 1], b[g >> 1][(g & 1) + 2]);
            }
        }
        __syncthreads();
    }

    const int qrow = lane >> 2;
    const int qcol = (lane & 3) * 2;
#pragma unroll
    for (int f = 0; f < 4; f++) {
        const size_t gr = m0 + wm * 64 + f * 16 + qrow;
#pragma unroll
        for (int g = 0; g < 4; g++) {
            const int lc = wn * 32 + g * 8 + qcol;
            const float b0 = s_bias[lc], b1 = s_bias[lc + 1];
            float* p0 = g_xg + gr * G3 + n0 + lc;
            float* p1 = p0 + 8 * G3;
            *(float2*)p0 = make_float2(acc[f][g][0] + b0, acc[f][g][1] + b1);
            *(float2*)p1 = make_float2(acc[f][g][2] + b0, acc[f][g][3] + b1);
        }
    }
}

// ===========================================================================
// Kernel 2: GRU scan — register weights, k-eighth split (2 units/thread).
// Thread (upair = tid>>3, ke = tid&7): holds 2 units x 3 gates x 32 k in
// 192 regs. Per step: 4-batch eighth-matvec (h 512B from smem, 4-way lane
// broadcast), xor4 unit specialization, xor1/xor2 batch specialization,
// gate math for (myu = upair*2 + (ke>>2), myb = ke&3). st.async exchange.
// hbuf k-eighth stride 36 floats -> 8 disjoint bank groups.
// ===========================================================================
#define HE  36                 // k-eighth stride (floats)
#define HBS8 (8 * HE)          // per-batch stride = 288

__device__ __forceinline__ float fast_sig(float x) {
    float xc = fminf(fmaxf(x, -80.f), 80.f);
    return __fdividef(1.f, 1.f + __expf(-xc));
}
__device__ __forceinline__ float fast_tanh(float x) {
    float xc = fminf(fmaxf(x, -40.f), 40.f);
    return 1.f - __fdividef(2.f, __expf(2.f * xc) + 1.f);
}

__global__ void __cluster_dims__(4, 1, 1) __launch_bounds__(256, 1)
scan_kernel(const float* __restrict__ rel_pos, const float* __restrict__ alpha,
            const float* __restrict__ W_hh, const float* __restrict__ b_hh)
{
    __shared__ __align__(16) float hbuf[2 * 4 * HBS8];   // [parity][b][288]
    __shared__ __align__(8) unsigned long long s_mbar[2];

    cg::cluster_group cluster = cg::this_cluster();
    const int crank = cluster.block_rank();
    const int cid   = blockIdx.x >> 2;
    const int tid   = threadIdx.x;
    const int upair = tid >> 3;                 // 0..31
    const int ke    = tid & 7;                  // 0..7
    const int sel   = (ke >> 2) & 1;            // which of my 2 units is mine
    const int myu   = upair * 2 + sel;          // 0..63
    const int myb   = ke & 3;                   // 0..3

    if (tid == 0) {
        MBAR_INIT(smem_u32(&s_mbar[0]), 1);
        MBAR_INIT(smem_u32(&s_mbar[1]), 1);
        asm volatile("fence.mbarrier_init.release.cluster;" ::: "memory");
    }
    cluster.sync();

    // ---- weights: 2 units x 3 gates x 32 k (this k-eighth) ----
    ull w[6][16];
#pragma unroll
    for (int u2 = 0; u2 < 2; u2++) {
        const int uu = upair * 2 + u2;
#pragma unroll
        for (int g = 0; g < 3; g++) {
            const ulonglong2* p = (const ulonglong2*)(W_hh +
                (size_t)(g * 256 + crank * 64 + uu) * HH + ke * 32);
#pragma unroll
            for (int i = 0; i < 8; i++) {
                ulonglong2 v = __ldg(p + i);
                w[u2 * 3 + g][2 * i] = v.x;
                w[u2 * 3 + g][2 * i + 1] = v.y;
            }
        }
    }
    const float bias_r = __ldg(b_hh + 0 * 256 + crank * 64 + myu);
    const float bias_z = __ldg(b_hh + 1 * 256 + crank * 64 + myu);
    const float bias_n = __ldg(b_hh + 2 * 256 + crank * 64 + myu);

    const int batch = cid * 4 + myb;
    const float a = fabsf(__ldg(alpha));

    const float* rp = rel_pos + (size_t)batch * SS;
    const float* xg_base = g_xg + ((size_t)batch * SS) * G3 + crank * 64 + myu;
    float* hs_base = g_hs + ((size_t)batch * SS) * HH + crank * 64 + myu;

    // remote addresses for this thread's h slot (batch myb, global unit idx)
    uint32_t rhb[4], rmb[4];
    {
        const int gidx = crank * 64 + myu;          // 0..255
        const int slot = gidx >> 5, j = gidx & 31;
        uint32_t lslot = smem_u32(&hbuf[myb * HBS8 + slot * HE + j]);
        uint32_t lmbar = smem_u32(&s_mbar[0]);
#pragma unroll
        for (int r = 0; r < 4; r++) {
            MAPA_U32(rhb[r], lslot, r);
            MAPA_U32(rmb[r], lmbar, r);
        }
    }
    const uint32_t lmb = smem_u32(&s_mbar[0]);

    // prefetch t = 0
    float rpt = __ldg(rp);
    float xr = __ldg(xg_base), xz = __ldg(xg_base + 256), xn = __ldg(xg_base + 512);

    float h = 0.0f, rp_prev = 0.0f;

    for (int t = 0; t < SS; t++) {
        const uint32_t ph    = (uint32_t)(t & 1);
        const uint32_t poffB = ph * (4 * HBS8 * 4);
        const uint32_t wp    = (uint32_t)((t >> 1) & 1);

        float dt = rpt - rp_prev;
        rp_prev = rpt;
        float hd = h * __expf(-a * dt);

        if (tid == 0) MBAR_EXPECT_TX(lmb + ph * 8, 4096u);
        ST_ASYNC_F32(rhb[0] + poffB, hd, rmb[0] + ph * 8);
        ST_ASYNC_F32(rhb[1] + poffB, hd, rmb[1] + ph * 8);
        ST_ASYNC_F32(rhb[2] + poffB, hd, rmb[2] + ph * 8);
        ST_ASYNC_F32(rhb[3] + poffB, hd, rmb[3] + ph * 8);

        const int tn = (t + 1 < SS) ? (t + 1) : (SS - 1);
        const float* xgn = xg_base + (size_t)tn * G3;
        float xr_n = __ldg(xgn), xz_n = __ldg(xgn + 256), xn_n = __ldg(xgn + 512);
        float rpt_n = __ldg(rp + tn);

        MBAR_WAIT_CL(lmb + ph * 8, wp);

        const int poff = ph * (4 * HBS8);
        float part[4][3];
#pragma unroll
        for (int b = 0; b < 4; b++) {
            const ulonglong2* hb =
                (const ulonglong2*)(hbuf + poff + b * HBS8 + ke * HE);
            ull acc[6];
#pragma unroll
            for (int r6 = 0; r6 < 6; r6++) acc[r6] = 0ull;
#pragma unroll
            for (int i = 0; i < 8; i++) {
                ulonglong2 hv = hb[i];
#pragma unroll
                for (int r6 = 0; r6 < 6; r6++) {
                    FMA2(acc[r6], w[r6][2 * i], hv.x);
                    FMA2(acc[r6], w[r6][2 * i + 1], hv.y);
                }
            }
            // collapse + unit specialization (xor 4)
#pragma unroll
            for (int g = 0; g < 3; g++) {
                float2 fo = *(float2*)&acc[sel * 3 + g];
                float2 fx = *(float2*)&acc[(1 - sel) * 3 + g];
                float own = fo.x + fo.y;
                float oth = fx.x + fx.y;
                part[b][g] = own + __shfl_xor_sync(0xFFFFFFFFu, oth, 4);
            }
        }

        // batch specialization: xor1 (bit0), then xor2 (bit1)
        const int b0 = ke & 1;
        const int b1 = (ke >> 1) & 1;
        float q[2][3];
#pragma unroll
        for (int bb = 0; bb < 2; bb++)
#pragma unroll
            for (int g = 0; g < 3; g++) {
                float keep = part[bb * 2 + b0][g];
                float send = part[bb * 2 + (b0 ^ 1)][g];
                q[bb][g] = keep + __shfl_xor_sync(0xFFFFFFFFu, send, 1);
            }
        float hr, hz, hnv;
        {
            float kr = q[b1][0], kz = q[b1][1], kn = q[b1][2];
            float sr = q[b1 ^ 1][0], sz = q[b1 ^ 1][1], sn = q[b1 ^ 1][2];
            hr  = kr + __shfl_xor_sync(0xFFFFFFFFu, sr, 2);
            hz  = kz + __shfl_xor_sync(0xFFFFFFFFu, sz, 2);
            hnv = kn + __shfl_xor_sync(0xFFFFFFFFu, sn, 2);
        }

        float r = fast_sig(xr + hr + bias_r);
        float z = fast_sig(xz + hz + bias_z);
        float n = fast_tanh(xn + (hnv + bias_n) * r);
        h = n + z * (hd - n);

        hs_base[(size_t)t * HH] = h;

        xr = xr_n; xz = xz_n; xn = xn_n; rpt = rpt_n;
    }

    cluster.sync();
}

// ===========================================================================
// Kernel 3: out = hs @ W_fc^T + b_fc.
// ===========================================================================
__global__ __launch_bounds__(256) void fc_kernel(
    const float* __restrict__ W_fc, const float* __restrict__ b_fc,
    float* __restrict__ out)
{
    __shared__ float Wsm[OO * HH];
    __shared__ float bsm[OO];
    const int tid = threadIdx.x;
    for (int i = tid; i < OO * HH; i += 256) Wsm[i] = W_fc[i];
    if (tid < OO) bsm[tid] = b_fc[tid];
    __syncthreads();

    const int warp = tid >> 5, lane = tid & 31;
    const size_t m = (size_t)blockIdx.x * 8 + warp;

    const float4* hp = (const float4*)(g_hs + m * HH + lane * 8);
    float4 hv0 = hp[0], hv1 = hp[1];

    float acc[OO];
#pragma unroll
    for (int o = 0; o < OO; o++) {
        const float* w = Wsm + o * HH + lane * 8;
        float4 w0 = *(const float4*)w;
        float4 w1 = *(const float4*)(w + 4);
        float s;
        s = hv0.x * w0.x;
        s = fmaf(hv0.y, w0.y, s);
        s = fmaf(hv0.z, w0.z, s);
        s = fmaf(hv0.w, w0.w, s);
        s = fmaf(hv1.x, w1.x, s);
        s = fmaf(hv1.y, w1.y, s);
        s = fmaf(hv1.z, w1.z, s);
        s = fmaf(hv1.w, w1.w, s);
        acc[o] = s;
    }
#pragma unroll
    for (int sft = 16; sft; sft >>= 1)
#pragma unroll
        for (int o = 0; o < OO; o++)
            acc[o] += __shfl_xor_sync(0xFFFFFFFFu, acc[o], sft);

    if (lane == 0) {
#pragma unroll
        for (int o = 0; o < OO; o++)
            out[m * OO + o] = acc[o] + bsm[o];
    }
}

// ===========================================================================
// Launch
// ===========================================================================
extern "C" void kernel_launch(void* const* d_in, const int* in_sizes, int n_in,
                              void* d_out, int out_size)
{
    const float* x       = (const float*)d_in[0];
    const float* rel_pos = (const float*)d_in[1];
    const float* alpha   = (const float*)d_in[2];
    const float* W_ih    = (const float*)d_in[3];
    const float* b_ih    = (const float*)d_in[4];
    const float* W_hh    = (const float*)d_in[5];
    const float* b_hh    = (const float*)d_in[6];
    const float* W_fc    = (const float*)d_in[7];
    const float* b_fc    = (const float*)d_in[8];
    float* out = (float*)d_out;

    (void)in_sizes; (void)n_in; (void)out_size;

    // 0) bf16 hi/lo packing (A' = [hi|lo], B' = [Wh|Wl|Wh])
    convert_x_kernel<<<MM, 192>>>(x);
    convert_w_kernel<<<G3, 192>>>(W_ih);

    // 1) Input projection via mma.sync (6 n-tiles x 1024 m-tiles)
    cudaFuncSetAttribute(gemm_mma_kernel,
                         cudaFuncAttributeMaxDynamicSharedMemorySize,
                         NSTG * STG_BYTES);
    dim3 ggrid(6, 1024);
    gemm_mma_kernel<<<ggrid, 256, NSTG * STG_BYTES>>>(b_ih);

    // 2) Scan (4-CTA clusters, register weights, k-eighth split)
    scan_kernel<<<128, 256>>>(rel_pos, alpha, W_hh, b_hh);

    // 3) Output FC
    fc_kernel<<<MM / 8, 256>>>(W_fc, b_fc, out);
}

// round 11
// speedup vs baseline: 1.3742x; 1.3742x over previous
#include <cuda_runtime.h>
#include <cuda_bf16.h>
#include <cooperative_groups.h>
#include <cstdint>

namespace cg = cooperative_groups;

// Problem constants
#define BB 128          // batch
#define SS 1024         // seq
#define II 768          // input dim
#define HH 256          // hidden
#define OO 6            // output
#define MM (BB * SS)    // 131072 rows
#define G3 (3 * HH)     // 768 gate rows

#define KP   2304       // packed K' = 3*768 (bf16 hi|hi|lo)
#define KPB  (KP * 2)   // 4608 bytes per packed row
#define NCHUNK (KP / 64)    // 36
#define NSTG 3
#define STG_BYTES 32768     // A 16KB + B 16KB

typedef unsigned long long ull;

// ---------------------------------------------------------------------------
// Scratch (device globals — allocation-free rule)
// ---------------------------------------------------------------------------
__device__ __align__(128) float g_xg[(size_t)MM * G3];           // [M, 768]
__device__ __align__(128) float g_hs[(size_t)MM * HH];           // [M, 256]
__device__ __align__(128) __nv_bfloat16 g_ax[(size_t)MM * KP];   // packed A'
__device__ __align__(128) __nv_bfloat16 g_bx[(size_t)G3 * KP];   // packed B'

// ---------------------------------------------------------------------------
// Generic-PTX helpers
// ---------------------------------------------------------------------------
__device__ __forceinline__ uint32_t smem_u32(const void* p) {
    uint32_t r;
    asm("{ .reg .u64 t; cvta.to.shared.u64 t, %1; cvt.u32.u64 %0, t; }"
        : "=r"(r) : "l"(p));
    return r;
}

__device__ __forceinline__ void cpa16(uint32_t saddr, const char* g) {
    asm volatile("cp.async.cg.shared.global [%0], [%1], 16;" :: "r"(saddr), "l"(g));
}

#define LDSM_X4(r, addr) \
    asm volatile("ldmatrix.sync.aligned.m8n8.x4.shared.b16 {%0,%1,%2,%3}, [%4];" \
                 : "=r"((r)[0]), "=r"((r)[1]), "=r"((r)[2]), "=r"((r)[3]) : "r"(addr))

#define MMA_16816(d, a, b0, b1) \
    asm volatile("mma.sync.aligned.m16n8k16.row.col.f32.bf16.bf16.f32 " \
                 "{%0,%1,%2,%3}, {%4,%5,%6,%7}, {%8,%9}, {%0,%1,%2,%3};" \
                 : "+f"((d)[0]), "+f"((d)[1]), "+f"((d)[2]), "+f"((d)[3]) \
                 : "r"((a)[0]), "r"((a)[1]), "r"((a)[2]), "r"((a)[3]), \
                   "r"(b0), "r"(b1))

#define FMA2(acc, a, b) \
    asm("fma.rn.f32x2 %0, %1, %2, %0;" : "+l"(acc) : "l"(a), "l"(b))

#define MBAR_INIT(addr, cnt) \
    asm volatile("mbarrier.init.shared.b64 [%0], %1;" :: "r"(addr), "r"(cnt) : "memory")

#define MBAR_EXPECT_TX(addr, tx) \
    asm volatile("mbarrier.arrive.expect_tx.shared.b64 _, [%0], %1;" \
                 :: "r"(addr), "r"(tx) : "memory")

#define MBAR_ARRIVE(addr) \
    asm volatile("mbarrier.arrive.shared.b64 _, [%0];" :: "r"(addr) : "memory")

#define MBAR_WAIT_CL(addr, parity) do {                                        \
    uint32_t _m = (addr); uint32_t _p = (parity); uint32_t _d;                 \
    asm volatile("{\n\t.reg .pred p;\n\t"                                      \
        "mbarrier.try_wait.parity.acquire.cluster.shared::cta.b64 p, [%1], %2;\n\t" \
        "selp.b32 %0, 1, 0, p;\n\t}"                                           \
        : "=r"(_d) : "r"(_m), "r"(_p) : "memory");                             \
    if (!_d) {                                                                 \
        asm volatile("{\n\t.reg .pred P1;\n\t"                                 \
            "W_%=:\n\t"                                                        \
            "mbarrier.try_wait.parity.acquire.cluster.shared::cta.b64 P1, [%0], %1, 0x989680;\n\t" \
            "@P1 bra.uni D_%=;\n\t"                                            \
            "bra.uni W_%=;\n\t"                                                \
            "D_%=:\n\t}" :: "r"(_m), "r"(_p) : "memory");                      \
    }                                                                          \
} while (0)

#define ST_ASYNC_F32(raddr, val, rmbar) \
    asm volatile("st.async.shared::cluster.mbarrier::complete_tx::bytes.b32 [%0], %1, [%2];" \
                 :: "r"(raddr), "r"(__float_as_uint(val)), "r"(rmbar) : "memory")

#define MAPA_U32(out, local, rank) \
    asm("mapa.shared::cluster.u32 %0, %1, %2;" : "=r"(out) : "r"(local), "r"(rank))

// ===========================================================================
// Convert kernels: split fp32 -> bf16 hi/lo, pack K' = [hi | hi | lo]
// (R8 layout — known good)
// ===========================================================================
__global__ __launch_bounds__(192) void convert_x_kernel(const float* __restrict__ x)
{
    const size_t row = blockIdx.x;
    const int t = threadIdx.x;
    float4 v = __ldg((const float4*)(x + row * II) + t);
    __nv_bfloat16 h0 = __float2bfloat16_rn(v.x);
    __nv_bfloat16 h1 = __float2bfloat16_rn(v.y);
    __nv_bfloat16 h2 = __float2bfloat16_rn(v.z);
    __nv_bfloat16 h3 = __float2bfloat16_rn(v.w);
    __nv_bfloat16 l0 = __float2bfloat16_rn(v.x - __bfloat162float(h0));
    __nv_bfloat16 l1 = __float2bfloat16_rn(v.y - __bfloat162float(h1));
    __nv_bfloat16 l2 = __float2bfloat16_rn(v.z - __bfloat162float(h2));
    __nv_bfloat16 l3 = __float2bfloat16_rn(v.w - __bfloat162float(h3));
    __nv_bfloat162 hp0 = __halves2bfloat162(h0, h1);
    __nv_bfloat162 hp1 = __halves2bfloat162(h2, h3);
    __nv_bfloat162 lp0 = __halves2bfloat162(l0, l1);
    __nv_bfloat162 lp1 = __halves2bfloat162(l2, l3);
    __nv_bfloat162* base = (__nv_bfloat162*)(g_ax + row * KP);
    base[t * 2]       = hp0;  base[t * 2 + 1]       = hp1;
    base[384 + t * 2] = hp0;  base[384 + t * 2 + 1] = hp1;
    base[768 + t * 2] = lp0;  base[768 + t * 2 + 1] = lp1;
}

__global__ __launch_bounds__(192) void convert_w_kernel(const float* __restrict__ W)
{
    const size_t row = blockIdx.x;
    const int t = threadIdx.x;
    float4 v = __ldg((const float4*)(W + row * II) + t);
    __nv_bfloat16 h0 = __float2bfloat16_rn(v.x);
    __nv_bfloat16 h1 = __float2bfloat16_rn(v.y);
    __nv_bfloat16 h2 = __float2bfloat16_rn(v.z);
    __nv_bfloat16 h3 = __float2bfloat16_rn(v.w);
    __nv_bfloat16 l0 = __float2bfloat16_rn(v.x - __bfloat162float(h0));
    __nv_bfloat16 l1 = __float2bfloat16_rn(v.y - __bfloat162float(h1));
    __nv_bfloat16 l2 = __float2bfloat16_rn(v.z - __bfloat162float(h2));
    __nv_bfloat16 l3 = __float2bfloat16_rn(v.w - __bfloat162float(h3));
    __nv_bfloat162 hp0 = __halves2bfloat162(h0, h1);
    __nv_bfloat162 hp1 = __halves2bfloat162(h2, h3);
    __nv_bfloat162 lp0 = __halves2bfloat162(l0, l1);
    __nv_bfloat162 lp1 = __halves2bfloat162(l2, l3);
    // B' = [Wh | Wl | Wh] pairs with A' = [xh | xh | xl]
    __nv_bfloat162* base = (__nv_bfloat162*)(g_bx + row * KP);
    base[t * 2]       = hp0;  base[t * 2 + 1]       = hp1;
    base[384 + t * 2] = lp0;  base[384 + t * 2 + 1] = lp1;
    base[768 + t * 2] = hp0;  base[768 + t * 2 + 1] = hp1;
}

// ===========================================================================
// Kernel 1: xg = x @ W_ih^T + b_ih via mma.sync bf16 (exact R8 — known good)
// ===========================================================================
__global__ __launch_bounds__(256, 1) void gemm_mma_kernel(
    const float* __restrict__ bias)
{
    extern __shared__ __align__(1024) char dsm[];
    __shared__ float s_bias[128];

    const int tid  = threadIdx.x;
    const int lane = tid & 31;
    const int warp = tid >> 5;
    const int wm = warp >> 2;
    const int wn = warp & 3;
    const int n0 = blockIdx.x * 128;
    const size_t m0 = (size_t)blockIdx.y * 128;

    const uint32_t smem_base = smem_u32(dsm);

    if (tid < 128) s_bias[tid] = __ldg(bias + n0 + tid);

    const char* gA = (const char*)(g_ax) + m0 * KPB;
    const char* gB = (const char*)(g_bx) + (size_t)n0 * KPB;

    auto issue_loads = [&](int slot, int kbyte) {
        const uint32_t stgA = smem_base + slot * STG_BYTES;
        const uint32_t stgB = stgA + 16384;
#pragma unroll
        for (int i = 0; i < 4; i++) {
            int seg = tid + i * 256;
            int r = seg >> 3, c = seg & 7;
            uint32_t off = (uint32_t)(r * 128 + ((c ^ (r & 7)) << 4));
            const size_t goff = (size_t)r * KPB + kbyte + c * 16;
            cpa16(stgA + off, gA + goff);
            cpa16(stgB + off, gB + goff);
        }
    };

    const int lrow = (lane & 7) + ((lane >> 3) & 1) * 8;
    const int cp   = lane >> 4;
    const int arow = wm * 64 + lrow;
    const int brow = wn * 32 + lrow;

    float acc[4][4][4];
#pragma unroll
    for (int f = 0; f < 4; f++)
#pragma unroll
        for (int g = 0; g < 4; g++)
#pragma unroll
            for (int r = 0; r < 4; r++) acc[f][g][r] = 0.0f;

    issue_loads(0, 0);
    asm volatile("cp.async.commit_group;" ::: "memory");
    issue_loads(1, 128);
    asm volatile("cp.async.commit_group;" ::: "memory");

    for (int c = 0; c < NCHUNK; c++) {
        const int lc = c + 2;
        if (lc < NCHUNK) issue_loads(lc % NSTG, lc * 128);
        asm volatile("cp.async.commit_group;" ::: "memory");
        asm volatile("cp.async.wait_group 2;" ::: "memory");
        __syncthreads();

        const uint32_t stgA = smem_base + (c % NSTG) * STG_BYTES;
        const uint32_t stgB = stgA + 16384;

#pragma unroll
        for (int s = 0; s < 4; s++) {
            const int ach = ((2 * s + cp) ^ (arow & 7)) << 4;
            const int bch = ((2 * s + cp) ^ (brow & 7)) << 4;
            uint32_t a[4][4];
            uint32_t b[2][4];
#pragma unroll
            for (int f = 0; f < 4; f++)
                LDSM_X4(a[f], stgA + (uint32_t)((arow + f * 16) * 128 + ach));
#pragma unroll
            for (int g2 = 0; g2 < 2; g2++)
                LDSM_X4(b[g2], stgB + (uint32_t)((brow + g2 * 16) * 128 + bch));
#pragma unroll
            for (int f = 0; f < 4; f++) {
#pragma unroll
                for (int g = 0; g < 4; g++)
                    MMA_16816(acc[f][g], a[f], b[g >> 1][g & 1], b[g >> 1][(g & 1) + 2]);
            }
        }
        __syncthreads();
    }

    const int qrow = lane >> 2;
    const int qcol = (lane & 3) * 2;
#pragma unroll
    for (int f = 0; f < 4; f++) {
        const size_t gr = m0 + wm * 64 + f * 16 + qrow;
#pragma unroll
        for (int g = 0; g < 4; g++) {
            const int lc = wn * 32 + g * 8 + qcol;
            const float b0 = s_bias[lc], b1 = s_bias[lc + 1];
            float* p0 = g_xg + gr * G3 + n0 + lc;
            float* p1 = p0 + 8 * G3;
            *(float2*)p0 = make_float2(acc[f][g][0] + b0, acc[f][g][1] + b1);
            *(float2*)p1 = make_float2(acc[f][g][2] + b0, acc[f][g][3] + b1);
        }
    }
}

// ===========================================================================
// Kernel 2: GRU scan — R8 structure (register weights, k-quarter split)
// with three deltas:
//   (1) own-rank h via plain STS + mbarrier arrive (count=256); st.async
//       only to the 3 REMOTE ranks; expect_tx = 3072 B.
//   (2) decay factor exp precomputed in the prefetch window.
//   (3) clamp-free sigmoid/tanh.
// ===========================================================================
#define HQ  68                // hbuf quarter stride (floats)
#define HBS (4 * HQ)          // per-batch stride = 272

__device__ __forceinline__ float fast_sig(float x) {
    return __fdividef(1.f, 1.f + __expf(-x));
}
__device__ __forceinline__ float fast_tanh(float x) {
    return 1.f - __fdividef(2.f, __expf(2.f * x) + 1.f);
}

__global__ void __cluster_dims__(4, 1, 1) __launch_bounds__(256, 1)
scan_kernel(const float* __restrict__ rel_pos, const float* __restrict__ alpha,
            const float* __restrict__ W_hh, const float* __restrict__ b_hh)
{
    __shared__ __align__(16) float hbuf[2 * 4 * HBS];   // [parity][b][4*68]
    __shared__ __align__(8) unsigned long long s_mbar[2];

    cg::cluster_group cluster = cg::this_cluster();
    const int crank = cluster.block_rank();     // 0..3
    const int cid   = blockIdx.x >> 2;          // 0..31
    const int tid   = threadIdx.x;
    const int u  = tid >> 2;                    // 0..63
    const int kq = tid & 3;                     // 0..3 (k-quarter, also batch)

    if (tid == 0) {
        MBAR_INIT(smem_u32(&s_mbar[0]), 256);
        MBAR_INIT(smem_u32(&s_mbar[1]), 256);
        asm volatile("fence.mbarrier_init.release.cluster;" ::: "memory");
    }
    cluster.sync();

    // ---- load this thread's weight slice into registers (R8) ----
    ull wr[32], wz[32], wn[32];
    {
        const ulonglong2* p0 = (const ulonglong2*)(W_hh +
            (size_t)(0 * 256 + crank * 64 + u) * HH + kq * 64);
        const ulonglong2* p1 = (const ulonglong2*)(W_hh +
            (size_t)(1 * 256 + crank * 64 + u) * HH + kq * 64);
        const ulonglong2* p2 = (const ulonglong2*)(W_hh +
            (size_t)(2 * 256 + crank * 64 + u) * HH + kq * 64);
#pragma unroll
        for (int i = 0; i < 16; i++) {
            ulonglong2 va = __ldg(p0 + i); wr[2 * i] = va.x; wr[2 * i + 1] = va.y;
            ulonglong2 vb = __ldg(p1 + i); wz[2 * i] = vb.x; wz[2 * i + 1] = vb.y;
            ulonglong2 vc = __ldg(p2 + i); wn[2 * i] = vc.x; wn[2 * i + 1] = vc.y;
        }
    }
    const float bias_r = __ldg(b_hh + 0 * 256 + crank * 64 + u);
    const float bias_z = __ldg(b_hh + 1 * 256 + crank * 64 + u);
    const float bias_n = __ldg(b_hh + 2 * 256 + crank * 64 + u);

    const int batch = cid * 4 + kq;             // this thread's gate batch
    const float a = fabsf(__ldg(alpha));

    const float* rp = rel_pos + (size_t)batch * SS;
    const float* xg_base = g_xg + ((size_t)batch * SS) * G3 + crank * 64 + u;
    float* hs_base = g_hs + ((size_t)batch * SS) * HH + crank * 64 + u;

    // own slot (local STS) + 3 remote targets (st.async)
    float* lown = &hbuf[kq * HBS + crank * HQ + u];
    uint32_t rhb[3], rmb[3];
    {
        uint32_t lslot = smem_u32(lown);
        uint32_t lmbar = smem_u32(&s_mbar[0]);
        int idx = 0;
#pragma unroll
        for (int r = 0; r < 4; r++) {
            if (r != crank) {
                MAPA_U32(rhb[idx], lslot, r);
                MAPA_U32(rmb[idx], lmbar, r);
                idx++;
            }
        }
    }
    const uint32_t lmb = smem_u32(&s_mbar[0]);

    // prefetch t = 0
    float rpt = __ldg(rp);
    float xr = __ldg(xg_base), xz = __ldg(xg_base + 256), xn = __ldg(xg_base + 512);
    float dec = __expf(-a * rpt);               // dt(0) = rp[0] - 0

    float h = 0.0f;

    for (int t = 0; t < SS; t++) {
        const uint32_t ph    = (uint32_t)(t & 1);
        const int      poff  = (int)ph * (4 * HBS);     // float offset
        const uint32_t poffB = ph * (uint32_t)(4 * HBS * 4);
        const uint32_t wp    = (uint32_t)((t >> 1) & 1);

        // decay (exp precomputed) + local STS + remote async broadcast
        float hd = h * dec;
        lown[poff] = hd;
        if (tid == 0) MBAR_EXPECT_TX(lmb + ph * 8, 3072u);
        else          MBAR_ARRIVE(lmb + ph * 8);
        ST_ASYNC_F32(rhb[0] + poffB, hd, rmb[0] + ph * 8);
        ST_ASYNC_F32(rhb[1] + poffB, hd, rmb[1] + ph * 8);
        ST_ASYNC_F32(rhb[2] + poffB, hd, rmb[2] + ph * 8);

        // prefetch next xg / rel_pos / decay while exchange is in flight
        const int tn = (t + 1 < SS) ? (t + 1) : (SS - 1);
        const float* xgn = xg_base + (size_t)tn * G3;
        float xr_n = __ldg(xgn), xz_n = __ldg(xgn + 256), xn_n = __ldg(xgn + 512);
        float rpt_n = __ldg(rp + tn);
        float dec_n = __expf(-a * (rpt_n - rpt));

        MBAR_WAIT_CL(lmb + ph * 8, wp);

        // k-quarter matvec for all 4 batches (weights in registers) — R8
        float hr = 0.f, hz = 0.f, hnv = 0.f;
#pragma unroll
        for (int b = 0; b < 4; b++) {
            const ulonglong2* hb =
                (const ulonglong2*)(hbuf + poff + b * HBS + kq * HQ);
            ull ar = 0ull, az = 0ull, an = 0ull;
#pragma unroll
            for (int i = 0; i < 16; i++) {
                ulonglong2 hv = hb[i];
                FMA2(ar, wr[2 * i], hv.x); FMA2(ar, wr[2 * i + 1], hv.y);
                FMA2(az, wz[2 * i], hv.x); FMA2(az, wz[2 * i + 1], hv.y);
                FMA2(an, wn[2 * i], hv.x); FMA2(an, wn[2 * i + 1], hv.y);
            }
            float2 f;
            float pr, pz, pn;
            f = *(float2*)&ar; pr = f.x + f.y;
            f = *(float2*)&az; pz = f.x + f.y;
            f = *(float2*)&an; pn = f.x + f.y;
            pr += __shfl_xor_sync(0xFFFFFFFFu, pr, 1);
            pz += __shfl_xor_sync(0xFFFFFFFFu, pz, 1);
            pn += __shfl_xor_sync(0xFFFFFFFFu, pn, 1);
            pr += __shfl_xor_sync(0xFFFFFFFFu, pr, 2);
            pz += __shfl_xor_sync(0xFFFFFFFFu, pz, 2);
            pn += __shfl_xor_sync(0xFFFFFFFFu, pn, 2);
            if (kq == b) { hr = pr; hz = pz; hnv = pn; }
        }

        float r = fast_sig(xr + hr + bias_r);
        float z = fast_sig(xz + hz + bias_z);
        float n = fast_tanh(xn + (hnv + bias_n) * r);
        h = n + z * (hd - n);

        hs_base[(size_t)t * HH] = h;

        xr = xr_n; xz = xz_n; xn = xn_n; rpt = rpt_n; dec = dec_n;
    }

    // no CTA may exit while peers might still st.async into its smem
    cluster.sync();
}

// ===========================================================================
// Kernel 3: out = hs @ W_fc^T + b_fc.
// ===========================================================================
__global__ __launch_bounds__(256) void fc_kernel(
    const float* __restrict__ W_fc, const float* __restrict__ b_fc,
    float* __restrict__ out)
{
    __shared__ float Wsm[OO * HH];
    __shared__ float bsm[OO];
    const int tid = threadIdx.x;
    for (int i = tid; i < OO * HH; i += 256) Wsm[i] = W_fc[i];
    if (tid < OO) bsm[tid] = b_fc[tid];
    __syncthreads();

    const int warp = tid >> 5, lane = tid & 31;
    const size_t m = (size_t)blockIdx.x * 8 + warp;

    const float4* hp = (const float4*)(g_hs + m * HH + lane * 8);
    float4 hv0 = hp[0], hv1 = hp[1];

    float acc[OO];
#pragma unroll
    for (int o = 0; o < OO; o++) {
        const float* w = Wsm + o * HH + lane * 8;
        float4 w0 = *(const float4*)w;
        float4 w1 = *(const float4*)(w + 4);
        float s;
        s = hv0.x * w0.x;
        s = fmaf(hv0.y, w0.y, s);
        s = fmaf(hv0.z, w0.z, s);
        s = fmaf(hv0.w, w0.w, s);
        s = fmaf(hv1.x, w1.x, s);
        s = fmaf(hv1.y, w1.y, s);
        s = fmaf(hv1.z, w1.z, s);
        s = fmaf(hv1.w, w1.w, s);
        acc[o] = s;
    }
#pragma unroll
    for (int sft = 16; sft; sft >>= 1)
#pragma unroll
        for (int o = 0; o < OO; o++)
            acc[o] += __shfl_xor_sync(0xFFFFFFFFu, acc[o], sft);

    if (lane == 0) {
#pragma unroll
        for (int o = 0; o < OO; o++)
            out[m * OO + o] = acc[o] + bsm[o];
    }
}

// ===========================================================================
// Launch
// ===========================================================================
extern "C" void kernel_launch(void* const* d_in, const int* in_sizes, int n_in,
                              void* d_out, int out_size)
{
    const float* x       = (const float*)d_in[0];
    const float* rel_pos = (const float*)d_in[1];
    const float* alpha   = (const float*)d_in[2];
    const float* W_ih    = (const float*)d_in[3];
    const float* b_ih    = (const float*)d_in[4];
    const float* W_hh    = (const float*)d_in[5];
    const float* b_hh    = (const float*)d_in[6];
    const float* W_fc    = (const float*)d_in[7];
    const float* b_fc    = (const float*)d_in[8];
    float* out = (float*)d_out;

    (void)in_sizes; (void)n_in; (void)out_size;

    // 0) bf16 hi/lo packing (R8 layout)
    convert_x_kernel<<<MM, 192>>>(x);
    convert_w_kernel<<<G3, 192>>>(W_ih);

    // 1) Input projection via mma.sync (6 n-tiles x 1024 m-tiles)
    cudaFuncSetAttribute(gemm_mma_kernel,
                         cudaFuncAttributeMaxDynamicSharedMemorySize,
                         NSTG * STG_BYTES);
    dim3 ggrid(6, 1024);
    gemm_mma_kernel<<<ggrid, 256, NSTG * STG_BYTES>>>(b_ih);

    // 2) Scan (4-CTA clusters, register weights, local STS + 3x st.async)
    scan_kernel<<<128, 256>>>(rel_pos, alpha, W_hh, b_hh);

    // 3) Output FC
    fc_kernel<<<MM / 8, 256>>>(W_fc, b_fc, out);
}